// round 13
// baseline (speedup 1.0000x reference)
#include <cuda_runtime.h>
#include <math.h>
#include <stdint.h>

// Problem constants
#define BATCH 2
#define SEQ   2048
#define DMODEL 1024
#define NHEAD 16
#define HDIM  64
#define MTOT  (BATCH*SEQ)            // 4096
#define QKV_N (3*DMODEL)             // 3072
#define GK    1024

// Scratch (allocation-free: __device__ globals)
__device__ float g_qkv[3u * 4194304u];   // [3][B][H][S][hd]  (RNA-rounded tf32 values)
__device__ float g_attn[4194304u];       // [B][S][H*hd]      (RNA-rounded tf32 values)
__device__ float g_rx[4194304u];         // rna(x)
__device__ float g_rwqkv[3145728u];      // rna(w_qkv)
__device__ float g_rwproj[1048576u];     // rna(w_proj)

__device__ __forceinline__ float f32_to_tf32f(float x) {
    uint32_t r;
    asm("cvt.rna.tf32.f32 %0, %1;" : "=r"(r) : "f"(x));
    return __uint_as_float(r);
}

__device__ __forceinline__ float ex2f(float x) {
    float r;
    asm("ex2.approx.ftz.f32 %0, %1;" : "=f"(r) : "f"(x));
    return r;
}

__device__ __forceinline__ uint32_t smem_u32(const void* p) {
    uint32_t a;
    asm("{ .reg .u64 t; cvta.to.shared.u64 t, %1; cvt.u32.u64 %0, t; }" : "=r"(a) : "l"(p));
    return a;
}

__device__ __forceinline__ void cp_async16(uint32_t dst_smem, const void* src) {
    asm volatile("cp.async.cg.shared.global [%0], [%1], 16;" :: "r"(dst_smem), "l"(src));
}
#define CP_COMMIT() asm volatile("cp.async.commit_group;" ::: "memory")
#define CP_WAIT(n)  asm volatile("cp.async.wait_group %0;" :: "n"(n) : "memory")

__device__ __forceinline__ void mma_tf32_16x8x8(float* c,
                                                float a0, float a1, float a2, float a3,
                                                float b0, float b1) {
    asm volatile(
        "mma.sync.aligned.m16n8k8.row.col.f32.tf32.tf32.f32 "
        "{%0,%1,%2,%3}, {%4,%5,%6,%7}, {%8,%9}, {%0,%1,%2,%3};"
        : "+f"(c[0]), "+f"(c[1]), "+f"(c[2]), "+f"(c[3])
        : "r"(__float_as_uint(a0)), "r"(__float_as_uint(a1)),
          "r"(__float_as_uint(a2)), "r"(__float_as_uint(a3)),
          "r"(__float_as_uint(b0)), "r"(__float_as_uint(b1)));
}

// ---------------------------------------------------------------------------
// Prep: RNA-round x, w_qkv, w_proj into scratch.
// ---------------------------------------------------------------------------
#define PREP_N4 2097152
__global__ __launch_bounds__(256) void prep_round_kernel(
    const float* __restrict__ x,
    const float* __restrict__ w_qkv,
    const float* __restrict__ w_proj)
{
    int i = blockIdx.x * 256 + threadIdx.x;
    if (i >= PREP_N4) return;
    const float4* src;
    float4* dst;
    if (i < 1048576) {
        src = (const float4*)x + i;
        dst = (float4*)g_rx + i;
    } else if (i < 1048576 + 786432) {
        src = (const float4*)w_qkv + (i - 1048576);
        dst = (float4*)g_rwqkv + (i - 1048576);
    } else {
        src = (const float4*)w_proj + (i - 1048576 - 786432);
        dst = (float4*)g_rwproj + (i - 1048576 - 786432);
    }
    float4 v = *src;
    v.x = f32_to_tf32f(v.x); v.y = f32_to_tf32f(v.y);
    v.z = f32_to_tf32f(v.z); v.w = f32_to_tf32f(v.w);
    *dst = v;
}

// ---------------------------------------------------------------------------
// tf32 mma.sync GEMM, cp.async 3-stage ring, K-tile 32, depth-2 prefetch.
// (unchanged from R12 passing version)
// ---------------------------------------------------------------------------
#define GKT 32
#define LDS_STRIDE 36
#define G_STG_F   (128 * LDS_STRIDE)
#define G_STG_B   (G_STG_F * 4)
#define GEMM_SMEM (3 * 2 * G_STG_B)

__global__ __launch_bounds__(256, 2) void gemm_tc_kernel(
    const float* __restrict__ bias,
    float* __restrict__ out,
    int mode)
{
    extern __shared__ float gsm[];
    float* As = gsm;                 // [3][G_STG_F]
    float* Bs = gsm + 3 * G_STG_F;   // [3][G_STG_F]

    const float* A = (mode == 0) ? (const float*)g_rx    : (const float*)g_attn;
    const float* W = (mode == 0) ? (const float*)g_rwqkv : (const float*)g_rwproj;

    int tid  = threadIdx.x;
    int wid  = tid >> 5;
    int lane = tid & 31;
    int wm   = wid >> 2;
    int wn   = wid & 3;
    int g    = lane >> 2;
    int tig  = lane & 3;

    int m0 = blockIdx.y * 128;
    int n0 = blockIdx.x * 128;

    int crow = tid >> 3;             // 0..31
    int cc4  = (tid & 7) << 2;       // 0,4,...,28

    const float* Ab = A + (size_t)m0 * GK;
    const float* Wb = W + (size_t)n0 * GK;

    uint32_t smA = smem_u32(As);
    uint32_t smB = smem_u32(Bs);

    float c[4][4][4];
#pragma unroll
    for (int i = 0; i < 4; i++)
#pragma unroll
        for (int j = 0; j < 4; j++)
#pragma unroll
            for (int q = 0; q < 4; q++) c[i][j][q] = 0.f;

    const int NT = GK / GKT;   // 32

    auto issue_tile = [&](int t, int s) {
        int ko = t * GKT;
        uint32_t aB = smA + s * G_STG_B;
        uint32_t bB = smB + s * G_STG_B;
#pragma unroll
        for (int p = 0; p < 4; p++) {
            int row = crow + p * 32;
            uint32_t doff = (uint32_t)(row * LDS_STRIDE + cc4) * 4;
            cp_async16(aB + doff, Ab + (size_t)row * GK + ko + cc4);
            cp_async16(bB + doff, Wb + (size_t)row * GK + ko + cc4);
        }
        CP_COMMIT();
    };

    issue_tile(0, 0);
    issue_tile(1, 1);

    int stg = 0;
    for (int kt = 0; kt < NT; kt++) {
        if (kt + 1 < NT) { CP_WAIT(1); } else { CP_WAIT(0); }
        __syncthreads();

        if (kt + 2 < NT) {
            int ws = stg + 2; if (ws >= 3) ws -= 3;
            issue_tile(kt + 2, ws);
        }

        const float* as = As + stg * G_STG_F;
        const float* bs = Bs + stg * G_STG_F;
#pragma unroll
        for (int k8 = 0; k8 < 4; k8++) {
            int kc = k8 * 8 + tig;
            float af[4][4], bf[4][2];
#pragma unroll
            for (int mt = 0; mt < 4; mt++) {
                int r = wm * 64 + mt * 16 + g;
                af[mt][0] = as[(r + 0) * LDS_STRIDE + kc];
                af[mt][1] = as[(r + 8) * LDS_STRIDE + kc];
                af[mt][2] = as[(r + 0) * LDS_STRIDE + kc + 4];
                af[mt][3] = as[(r + 8) * LDS_STRIDE + kc + 4];
            }
#pragma unroll
            for (int nt = 0; nt < 4; nt++) {
                int r = wn * 32 + nt * 8 + g;
                bf[nt][0] = bs[r * LDS_STRIDE + kc];
                bf[nt][1] = bs[r * LDS_STRIDE + kc + 4];
            }
#pragma unroll
            for (int mt = 0; mt < 4; mt++)
#pragma unroll
                for (int nt = 0; nt < 4; nt++)
                    mma_tf32_16x8x8(c[mt][nt],
                                    af[mt][0], af[mt][1], af[mt][2], af[mt][3],
                                    bf[nt][0], bf[nt][1]);
        }
        stg = stg + 1; if (stg >= 3) stg = 0;
    }

    // Epilogue
#pragma unroll
    for (int mt = 0; mt < 4; mt++) {
#pragma unroll
        for (int half = 0; half < 2; half++) {
            int m = m0 + wm * 64 + mt * 16 + g + half * 8;
            int b = m >> 11;
            int s = m & 2047;
#pragma unroll
            for (int nt = 0; nt < 4; nt++) {
                int n = n0 + wn * 32 + nt * 8 + 2 * tig;
                float2 v;
                v.x = c[mt][nt][half * 2 + 0] + bias[n + 0];
                v.y = c[mt][nt][half * 2 + 1] + bias[n + 1];
                if (mode == 0) {
                    v.x = f32_to_tf32f(v.x);
                    v.y = f32_to_tf32f(v.y);
                    int which = n >> 10;
                    int rr = n & 1023;
                    int h = rr >> 6;
                    int d = rr & 63;
                    *(float2*)&g_qkv[(size_t)which * 4194304u +
                                     ((size_t)((b << 4) + h) * SEQ + s) * HDIM + d] = v;
                } else {
                    *(float2*)&out[(size_t)m * DMODEL + n] = v;
                }
            }
        }
    }
}

// ---------------------------------------------------------------------------
// Flash attention, cp.async 2-stage K/V ring, SINGLE barrier per tile.
// R13: issue for kt+1 moved AFTER the barrier (GEMM-proven ordering).
// barrier(kt) guarantees all warps finished compute(kt-1) — the only reader
// of stage cur^1 — so writing cur^1 right after the barrier is hazard-free.
// Prefetch distance = one full compute phase (~2500 cyc >> load latency).
// ---------------------------------------------------------------------------
#define KS_STRIDE 68
#define VS_STRIDE 72
#define PS_STRIDE 68
#define KS_STG_F (64 * KS_STRIDE)
#define VS_STG_F (64 * VS_STRIDE)
#define FLASH_SMEM ((2*KS_STG_F + 2*VS_STG_F + 128*PS_STRIDE) * 4)

__global__ __launch_bounds__(256, 2) void flash_tc_kernel()
{
    extern __shared__ float smf[];
    float* KsB = smf;                          // [2][KS_STG_F]
    float* VsB = smf + 2 * KS_STG_F;           // [2][VS_STG_F]
    float* Ps  = smf + 2 * KS_STG_F + 2 * VS_STG_F;  // [128][PS_STRIDE]

    int tid  = threadIdx.x;
    int w    = tid >> 5;
    int lane = tid & 31;
    int g    = lane >> 2;          // 0..7
    int tig  = lane & 3;           // 0..3

    int q0 = blockIdx.x * 128;
    int h  = blockIdx.y;
    int b  = blockIdx.z;

    const float scale = 0.125f * 1.4426950408889634f;

    const float* Qg = g_qkv + 0u * 4194304u + (size_t)((b << 4) + h) * SEQ * HDIM;
    const float* Kg = g_qkv + 1u * 4194304u + (size_t)((b << 4) + h) * SEQ * HDIM;
    const float* Vg = g_qkv + 2u * 4194304u + (size_t)((b << 4) + h) * SEQ * HDIM;

    uint32_t smK = smem_u32(KsB);
    uint32_t smV = smem_u32(VsB);

    int lrow = tid >> 4;             // 0..15
    int lc4  = (tid & 15) << 2;      // 0,4,...,60

    int qrow = q0 + w * 16;
    float qf[8][4];
#pragma unroll
    for (int kc = 0; kc < 8; kc++) {
        int d0 = kc * 8 + tig;
        qf[kc][0] = f32_to_tf32f(Qg[(size_t)(qrow + g)     * HDIM + d0]     * scale);
        qf[kc][1] = f32_to_tf32f(Qg[(size_t)(qrow + g + 8) * HDIM + d0]     * scale);
        qf[kc][2] = f32_to_tf32f(Qg[(size_t)(qrow + g)     * HDIM + d0 + 4] * scale);
        qf[kc][3] = f32_to_tf32f(Qg[(size_t)(qrow + g + 8) * HDIM + d0 + 4] * scale);
    }

    float m0r = -1e30f, m1r = -1e30f, l0r = 0.f, l1r = 0.f;
    float ov[8][4];
#pragma unroll
    for (int nt = 0; nt < 8; nt++)
#pragma unroll
        for (int q = 0; q < 4; q++) ov[nt][q] = 0.f;

    float* Psw = Ps + w * 16 * PS_STRIDE;

    const int NT = SEQ / 64;   // 32

    // prologue: issue tile 0 -> stage 0
    {
#pragma unroll
        for (int it = 0; it < 4; it++) {
            int row = lrow + it * 16;
            cp_async16(smK + (uint32_t)(row * KS_STRIDE + lc4) * 4,
                       Kg + (size_t)row * HDIM + lc4);
            cp_async16(smV + (uint32_t)(row * VS_STRIDE + lc4) * 4,
                       Vg + (size_t)row * HDIM + lc4);
        }
        CP_COMMIT();
    }

    for (int kt = 0; kt < NT; kt++) {
        int cur = kt & 1;

        CP_WAIT(0);                 // tile kt resident (issued one phase ago)
        __syncthreads();            // all warps done with stage cur^1 (tile kt-1)

        if (kt + 1 < NT) {          // refill the just-freed stage
            const float* Kn = Kg + (size_t)(kt + 1) * 64 * HDIM;
            const float* Vn = Vg + (size_t)(kt + 1) * 64 * HDIM;
            uint32_t kB = smK + (cur ^ 1) * (KS_STG_F * 4);
            uint32_t vB = smV + (cur ^ 1) * (VS_STG_F * 4);
#pragma unroll
            for (int it = 0; it < 4; it++) {
                int row = lrow + it * 16;
                cp_async16(kB + (uint32_t)(row * KS_STRIDE + lc4) * 4,
                           Kn + (size_t)row * HDIM + lc4);
                cp_async16(vB + (uint32_t)(row * VS_STRIDE + lc4) * 4,
                           Vn + (size_t)row * HDIM + lc4);
            }
            CP_COMMIT();
        }

        const float* Ks = KsB + cur * KS_STG_F;
        const float* Vs = VsB + cur * VS_STG_F;

        // S = Q K^T
        float sc[8][4];
#pragma unroll
        for (int nt = 0; nt < 8; nt++)
#pragma unroll
            for (int q = 0; q < 4; q++) sc[nt][q] = 0.f;
#pragma unroll
        for (int kc = 0; kc < 8; kc++) {
            int d0 = kc * 8 + tig;
#pragma unroll
            for (int nt = 0; nt < 8; nt++) {
                int key = nt * 8 + g;
                float b0 = Ks[key * KS_STRIDE + d0];
                float b1 = Ks[key * KS_STRIDE + d0 + 4];
                mma_tf32_16x8x8(sc[nt], qf[kc][0], qf[kc][1], qf[kc][2], qf[kc][3], b0, b1);
            }
        }

        // Online softmax (base-2).
        float rm0 = -1e30f, rm1 = -1e30f;
#pragma unroll
        for (int nt = 0; nt < 8; nt++) {
            rm0 = fmaxf(rm0, fmaxf(sc[nt][0], sc[nt][1]));
            rm1 = fmaxf(rm1, fmaxf(sc[nt][2], sc[nt][3]));
        }
        rm0 = fmaxf(rm0, __shfl_xor_sync(0xffffffffu, rm0, 1));
        rm0 = fmaxf(rm0, __shfl_xor_sync(0xffffffffu, rm0, 2));
        rm1 = fmaxf(rm1, __shfl_xor_sync(0xffffffffu, rm1, 1));
        rm1 = fmaxf(rm1, __shfl_xor_sync(0xffffffffu, rm1, 2));

        float nm0 = fmaxf(m0r, rm0);
        float nm1 = fmaxf(m1r, rm1);
        float alpha0 = ex2f(m0r - nm0);
        float alpha1 = ex2f(m1r - nm1);
        m0r = nm0; m1r = nm1;

        float rs0 = 0.f, rs1 = 0.f;
#pragma unroll
        for (int nt = 0; nt < 8; nt++) {
            sc[nt][0] = ex2f(sc[nt][0] - nm0);
            sc[nt][1] = ex2f(sc[nt][1] - nm0);
            sc[nt][2] = ex2f(sc[nt][2] - nm1);
            sc[nt][3] = ex2f(sc[nt][3] - nm1);
            rs0 += sc[nt][0] + sc[nt][1];
            rs1 += sc[nt][2] + sc[nt][3];
        }
        rs0 += __shfl_xor_sync(0xffffffffu, rs0, 1);
        rs0 += __shfl_xor_sync(0xffffffffu, rs0, 2);
        rs1 += __shfl_xor_sync(0xffffffffu, rs1, 1);
        rs1 += __shfl_xor_sync(0xffffffffu, rs1, 2);
        l0r = l0r * alpha0 + rs0;
        l1r = l1r * alpha1 + rs1;

#pragma unroll
        for (int nt = 0; nt < 8; nt++) {
            ov[nt][0] *= alpha0; ov[nt][1] *= alpha0;
            ov[nt][2] *= alpha1; ov[nt][3] *= alpha1;
        }

        // Stage P (RNA tf32) into per-warp slab
#pragma unroll
        for (int nt = 0; nt < 8; nt++) {
            float2 p0, p1;
            p0.x = f32_to_tf32f(sc[nt][0]); p0.y = f32_to_tf32f(sc[nt][1]);
            p1.x = f32_to_tf32f(sc[nt][2]); p1.y = f32_to_tf32f(sc[nt][3]);
            *(float2*)&Psw[g       * PS_STRIDE + nt * 8 + 2 * tig] = p0;
            *(float2*)&Psw[(g + 8) * PS_STRIDE + nt * 8 + 2 * tig] = p1;
        }
        __syncwarp();

        // O += P V
#pragma unroll
        for (int kc = 0; kc < 8; kc++) {
            int k0 = kc * 8 + tig;
            float a0 = Psw[g       * PS_STRIDE + k0];
            float a1 = Psw[(g + 8) * PS_STRIDE + k0];
            float a2 = Psw[g       * PS_STRIDE + k0 + 4];
            float a3 = Psw[(g + 8) * PS_STRIDE + k0 + 4];
#pragma unroll
            for (int nt = 0; nt < 8; nt++) {
                float b0 = Vs[k0       * VS_STRIDE + nt * 8 + g];
                float b1 = Vs[(k0 + 4) * VS_STRIDE + nt * 8 + g];
                mma_tf32_16x8x8(ov[nt], a0, a1, a2, a3, b0, b1);
            }
        }
        // no end-of-tile barrier: next iteration's barrier provides the guard
    }

    // Epilogue: normalize, RNA-round (proj cp.async identity), store.
    float inv0 = 1.0f / l0r;
    float inv1 = 1.0f / l1r;
    int s0 = qrow + g;
    int s1 = qrow + g + 8;
#pragma unroll
    for (int nt = 0; nt < 8; nt++) {
        int d = nt * 8 + 2 * tig;
        float2 v0, v1;
        v0.x = f32_to_tf32f(ov[nt][0] * inv0); v0.y = f32_to_tf32f(ov[nt][1] * inv0);
        v1.x = f32_to_tf32f(ov[nt][2] * inv1); v1.y = f32_to_tf32f(ov[nt][3] * inv1);
        *(float2*)&g_attn[((size_t)(b * SEQ + s0)) * DMODEL + h * HDIM + d] = v0;
        *(float2*)&g_attn[((size_t)(b * SEQ + s1)) * DMODEL + h * HDIM + d] = v1;
    }
}

// ---------------------------------------------------------------------------
// Launch
// ---------------------------------------------------------------------------
extern "C" void kernel_launch(void* const* d_in, const int* in_sizes, int n_in,
                              void* d_out, int out_size)
{
    const float* x      = (const float*)d_in[0];
    const float* w_qkv  = (const float*)d_in[1];
    const float* b_qkv  = (const float*)d_in[2];
    const float* w_proj = (const float*)d_in[3];
    const float* b_proj = (const float*)d_in[4];
    float* out = (float*)d_out;

    cudaFuncSetAttribute(gemm_tc_kernel, cudaFuncAttributeMaxDynamicSharedMemorySize, GEMM_SMEM);
    cudaFuncSetAttribute(flash_tc_kernel, cudaFuncAttributeMaxDynamicSharedMemorySize, FLASH_SMEM);

    prep_round_kernel<<<(PREP_N4 + 255) / 256, 256>>>(x, w_qkv, w_proj);
    gemm_tc_kernel<<<dim3(QKV_N / 128, MTOT / 128), 256, GEMM_SMEM>>>(b_qkv, nullptr, 0);
    flash_tc_kernel<<<dim3(SEQ / 128, NHEAD, BATCH), 256, FLASH_SMEM>>>();
    gemm_tc_kernel<<<dim3(DMODEL / 128, MTOT / 128), 256, GEMM_SMEM>>>(b_proj, out, 1);
}

// round 14
// speedup vs baseline: 1.0006x; 1.0006x over previous
#include <cuda_runtime.h>
#include <math.h>
#include <stdint.h>

// Problem constants
#define BATCH 2
#define SEQ   2048
#define DMODEL 1024
#define NHEAD 16
#define HDIM  64
#define MTOT  (BATCH*SEQ)            // 4096
#define QKV_N (3*DMODEL)             // 3072
#define GK    1024

// Scratch (allocation-free: __device__ globals)
__device__ float g_qkv[3u * 4194304u];   // [3][B][H][S][hd]  (RNA-rounded tf32 values)
__device__ float g_attn[4194304u];       // [B][S][H*hd]      (RNA-rounded tf32 values)
__device__ float g_rx[4194304u];         // rna(x)
__device__ float g_rwqkv[3145728u];      // rna(w_qkv)
__device__ float g_rwproj[1048576u];     // rna(w_proj)

__device__ __forceinline__ float f32_to_tf32f(float x) {
    uint32_t r;
    asm("cvt.rna.tf32.f32 %0, %1;" : "=r"(r) : "f"(x));
    return __uint_as_float(r);
}

__device__ __forceinline__ float ex2f(float x) {
    float r;
    asm("ex2.approx.ftz.f32 %0, %1;" : "=f"(r) : "f"(x));
    return r;
}

__device__ __forceinline__ uint32_t smem_u32(const void* p) {
    uint32_t a;
    asm("{ .reg .u64 t; cvta.to.shared.u64 t, %1; cvt.u32.u64 %0, t; }" : "=r"(a) : "l"(p));
    return a;
}

__device__ __forceinline__ void cp_async16(uint32_t dst_smem, const void* src) {
    asm volatile("cp.async.cg.shared.global [%0], [%1], 16;" :: "r"(dst_smem), "l"(src));
}
#define CP_COMMIT() asm volatile("cp.async.commit_group;" ::: "memory")
#define CP_WAIT(n)  asm volatile("cp.async.wait_group %0;" :: "n"(n) : "memory")

__device__ __forceinline__ void mma_tf32_16x8x8(float* c,
                                                float a0, float a1, float a2, float a3,
                                                float b0, float b1) {
    asm volatile(
        "mma.sync.aligned.m16n8k8.row.col.f32.tf32.tf32.f32 "
        "{%0,%1,%2,%3}, {%4,%5,%6,%7}, {%8,%9}, {%0,%1,%2,%3};"
        : "+f"(c[0]), "+f"(c[1]), "+f"(c[2]), "+f"(c[3])
        : "r"(__float_as_uint(a0)), "r"(__float_as_uint(a1)),
          "r"(__float_as_uint(a2)), "r"(__float_as_uint(a3)),
          "r"(__float_as_uint(b0)), "r"(__float_as_uint(b1)));
}

// ---------------------------------------------------------------------------
// Prep: RNA-round x, w_qkv, w_proj into scratch.  (unchanged)
// ---------------------------------------------------------------------------
#define PREP_N4 2097152
__global__ __launch_bounds__(256) void prep_round_kernel(
    const float* __restrict__ x,
    const float* __restrict__ w_qkv,
    const float* __restrict__ w_proj)
{
    int i = blockIdx.x * 256 + threadIdx.x;
    if (i >= PREP_N4) return;
    const float4* src;
    float4* dst;
    if (i < 1048576) {
        src = (const float4*)x + i;
        dst = (float4*)g_rx + i;
    } else if (i < 1048576 + 786432) {
        src = (const float4*)w_qkv + (i - 1048576);
        dst = (float4*)g_rwqkv + (i - 1048576);
    } else {
        src = (const float4*)w_proj + (i - 1048576 - 786432);
        dst = (float4*)g_rwproj + (i - 1048576 - 786432);
    }
    float4 v = *src;
    v.x = f32_to_tf32f(v.x); v.y = f32_to_tf32f(v.y);
    v.z = f32_to_tf32f(v.z); v.w = f32_to_tf32f(v.w);
    *dst = v;
}

// ---------------------------------------------------------------------------
// tf32 mma.sync GEMM, cp.async 3-stage ring, K-tile 32, depth-2 prefetch.
// (unchanged from R12 passing version)
// ---------------------------------------------------------------------------
#define GKT 32
#define LDS_STRIDE 36
#define G_STG_F   (128 * LDS_STRIDE)
#define G_STG_B   (G_STG_F * 4)
#define GEMM_SMEM (3 * 2 * G_STG_B)

__global__ __launch_bounds__(256, 2) void gemm_tc_kernel(
    const float* __restrict__ bias,
    float* __restrict__ out,
    int mode)
{
    extern __shared__ float gsm[];
    float* As = gsm;                 // [3][G_STG_F]
    float* Bs = gsm + 3 * G_STG_F;   // [3][G_STG_F]

    const float* A = (mode == 0) ? (const float*)g_rx    : (const float*)g_attn;
    const float* W = (mode == 0) ? (const float*)g_rwqkv : (const float*)g_rwproj;

    int tid  = threadIdx.x;
    int wid  = tid >> 5;
    int lane = tid & 31;
    int wm   = wid >> 2;
    int wn   = wid & 3;
    int g    = lane >> 2;
    int tig  = lane & 3;

    int m0 = blockIdx.y * 128;
    int n0 = blockIdx.x * 128;

    int crow = tid >> 3;             // 0..31
    int cc4  = (tid & 7) << 2;       // 0,4,...,28

    const float* Ab = A + (size_t)m0 * GK;
    const float* Wb = W + (size_t)n0 * GK;

    uint32_t smA = smem_u32(As);
    uint32_t smB = smem_u32(Bs);

    float c[4][4][4];
#pragma unroll
    for (int i = 0; i < 4; i++)
#pragma unroll
        for (int j = 0; j < 4; j++)
#pragma unroll
            for (int q = 0; q < 4; q++) c[i][j][q] = 0.f;

    const int NT = GK / GKT;   // 32

    auto issue_tile = [&](int t, int s) {
        int ko = t * GKT;
        uint32_t aB = smA + s * G_STG_B;
        uint32_t bB = smB + s * G_STG_B;
#pragma unroll
        for (int p = 0; p < 4; p++) {
            int row = crow + p * 32;
            uint32_t doff = (uint32_t)(row * LDS_STRIDE + cc4) * 4;
            cp_async16(aB + doff, Ab + (size_t)row * GK + ko + cc4);
            cp_async16(bB + doff, Wb + (size_t)row * GK + ko + cc4);
        }
        CP_COMMIT();
    };

    issue_tile(0, 0);
    issue_tile(1, 1);

    int stg = 0;
    for (int kt = 0; kt < NT; kt++) {
        if (kt + 1 < NT) { CP_WAIT(1); } else { CP_WAIT(0); }
        __syncthreads();

        if (kt + 2 < NT) {
            int ws = stg + 2; if (ws >= 3) ws -= 3;
            issue_tile(kt + 2, ws);
        }

        const float* as = As + stg * G_STG_F;
        const float* bs = Bs + stg * G_STG_F;
#pragma unroll
        for (int k8 = 0; k8 < 4; k8++) {
            int kc = k8 * 8 + tig;
            float af[4][4], bf[4][2];
#pragma unroll
            for (int mt = 0; mt < 4; mt++) {
                int r = wm * 64 + mt * 16 + g;
                af[mt][0] = as[(r + 0) * LDS_STRIDE + kc];
                af[mt][1] = as[(r + 8) * LDS_STRIDE + kc];
                af[mt][2] = as[(r + 0) * LDS_STRIDE + kc + 4];
                af[mt][3] = as[(r + 8) * LDS_STRIDE + kc + 4];
            }
#pragma unroll
            for (int nt = 0; nt < 4; nt++) {
                int r = wn * 32 + nt * 8 + g;
                bf[nt][0] = bs[r * LDS_STRIDE + kc];
                bf[nt][1] = bs[r * LDS_STRIDE + kc + 4];
            }
#pragma unroll
            for (int mt = 0; mt < 4; mt++)
#pragma unroll
                for (int nt = 0; nt < 4; nt++)
                    mma_tf32_16x8x8(c[mt][nt],
                                    af[mt][0], af[mt][1], af[mt][2], af[mt][3],
                                    bf[nt][0], bf[nt][1]);
        }
        stg = stg + 1; if (stg >= 3) stg = 0;
    }

    // Epilogue
#pragma unroll
    for (int mt = 0; mt < 4; mt++) {
#pragma unroll
        for (int half = 0; half < 2; half++) {
            int m = m0 + wm * 64 + mt * 16 + g + half * 8;
            int b = m >> 11;
            int s = m & 2047;
#pragma unroll
            for (int nt = 0; nt < 4; nt++) {
                int n = n0 + wn * 32 + nt * 8 + 2 * tig;
                float2 v;
                v.x = c[mt][nt][half * 2 + 0] + bias[n + 0];
                v.y = c[mt][nt][half * 2 + 1] + bias[n + 1];
                if (mode == 0) {
                    v.x = f32_to_tf32f(v.x);
                    v.y = f32_to_tf32f(v.y);
                    int which = n >> 10;
                    int rr = n & 1023;
                    int h = rr >> 6;
                    int d = rr & 63;
                    *(float2*)&g_qkv[(size_t)which * 4194304u +
                                     ((size_t)((b << 4) + h) * SEQ + s) * HDIM + d] = v;
                } else {
                    *(float2*)&out[(size_t)m * DMODEL + n] = v;
                }
            }
        }
    }
}

// ---------------------------------------------------------------------------
// Flash attention — R14: permuted-K S-phase with LDS.128 fragment loads.
// K arrives raw via cp.async (single strip), repacked into KsP where thread
// (g,tig)'s 16 B-fragment values per key are 4 contiguous float4s:
//   KsP[key][20c + 4t + e] = K[key][16c + 4e + t]   (row stride 80)
// S-phase B reads: 128 LDS.32 -> 32 LDS.128 per warp per tile (conflict-free;
// 16B-group = (4g + 5c + tig) mod 8 is a transversal per quarter-warp).
// Fragments: b0 = kb[2kc], b1 = kb[2kc+1].
// V path (cp.async 2-stage) and PV phase unchanged.
// Smem floats: Kraw[64][64] | Vs[2][64][72] | KsP[64][80] | Ps[128][68]
//            = 4096 + 9216 + 5120 + 8704 = 27136 -> 108544 B (2 CTAs/SM ok).
// ---------------------------------------------------------------------------
#define VS_STRIDE 72
#define PS_STRIDE 68
#define KRAW_F   (64 * 64)
#define VS_STG_F (64 * VS_STRIDE)
#define KSP_F    (64 * 80)
#define FLASH_SMEM ((KRAW_F + 2*VS_STG_F + KSP_F + 128*PS_STRIDE) * 4)

__global__ __launch_bounds__(256, 2) void flash_tc_kernel()
{
    extern __shared__ float smf[];
    float* Kraw = smf;                             // [64][64]
    float* VsB  = smf + KRAW_F;                    // [2][64][VS_STRIDE]
    float* KsP  = smf + KRAW_F + 2 * VS_STG_F;     // [64][80] permuted
    float* Ps   = smf + KRAW_F + 2 * VS_STG_F + KSP_F;  // [128][PS_STRIDE]

    int tid  = threadIdx.x;
    int w    = tid >> 5;
    int lane = tid & 31;
    int g    = lane >> 2;          // 0..7
    int tig  = lane & 3;           // 0..3

    int q0 = blockIdx.x * 128;
    int h  = blockIdx.y;
    int b  = blockIdx.z;

    const float scale = 0.125f * 1.4426950408889634f;

    const float* Qg = g_qkv + 0u * 4194304u + (size_t)((b << 4) + h) * SEQ * HDIM;
    const float* Kg = g_qkv + 1u * 4194304u + (size_t)((b << 4) + h) * SEQ * HDIM;
    const float* Vg = g_qkv + 2u * 4194304u + (size_t)((b << 4) + h) * SEQ * HDIM;

    uint32_t smKraw = smem_u32(Kraw);
    uint32_t smV    = smem_u32(VsB);

    int m16  = tid & 15;             // 0..15
    int lrow = tid >> 4;             // 0..15
    int lc4  = m16 << 2;             // 0,4,...,60

    // Q fragments, register-resident (scale + tf32 RNA folded)
    int qrow = q0 + w * 16;
    float qf[8][4];
#pragma unroll
    for (int kc = 0; kc < 8; kc++) {
        int d0 = kc * 8 + tig;
        qf[kc][0] = f32_to_tf32f(Qg[(size_t)(qrow + g)     * HDIM + d0]     * scale);
        qf[kc][1] = f32_to_tf32f(Qg[(size_t)(qrow + g + 8) * HDIM + d0]     * scale);
        qf[kc][2] = f32_to_tf32f(Qg[(size_t)(qrow + g)     * HDIM + d0 + 4] * scale);
        qf[kc][3] = f32_to_tf32f(Qg[(size_t)(qrow + g + 8) * HDIM + d0 + 4] * scale);
    }

    float m0r = -1e30f, m1r = -1e30f, l0r = 0.f, l1r = 0.f;
    float ov[8][4];
#pragma unroll
    for (int nt = 0; nt < 8; nt++)
#pragma unroll
        for (int q = 0; q < 4; q++) ov[nt][q] = 0.f;

    float* Psw = Ps + w * 16 * PS_STRIDE;

    const int NT = SEQ / 64;   // 32

    // prologue: issue K(0) -> Kraw, V(0) -> Vs stage 0
    {
#pragma unroll
        for (int it = 0; it < 4; it++) {
            int row = lrow + it * 16;
            cp_async16(smKraw + (uint32_t)(row * 64 + lc4) * 4,
                       Kg + (size_t)row * HDIM + lc4);
            cp_async16(smV + (uint32_t)(row * VS_STRIDE + lc4) * 4,
                       Vg + (size_t)row * HDIM + lc4);
        }
        CP_COMMIT();
    }

    // repack destination base for this thread (within a row):
    // element e of the thread's float4 (d = 4*m16 + e) goes to
    // row*80 + 20*(m16>>2) + (m16&3) + 4*e
    int rp_base = 20 * (m16 >> 2) + (m16 & 3);

    for (int kt = 0; kt < NT; kt++) {
        int cur = kt & 1;

        CP_WAIT(0);                 // K(kt) raw + V(kt) resident
        __syncthreads();            // prev compute done (KsP + Vs[cur^1] + Kraw free)

        // Repack K raw -> KsP (4 x LDS.128 + 16 x STS.32 per warp; conflict-free)
#pragma unroll
        for (int it = 0; it < 4; it++) {
            int row = lrow + it * 16;
            float4 r = *(const float4*)&Kraw[row * 64 + lc4];
            float* dstp = &KsP[row * 80 + rp_base];
            dstp[0]  = r.x;
            dstp[4]  = r.y;
            dstp[8]  = r.z;
            dstp[12] = r.w;
        }
        __syncthreads();            // KsP complete; all Kraw reads done

        if (kt + 1 < NT) {          // refill Kraw + Vs[cur^1] (both now free)
            const float* Kn = Kg + (size_t)(kt + 1) * 64 * HDIM;
            const float* Vn = Vg + (size_t)(kt + 1) * 64 * HDIM;
            uint32_t vB = smV + (cur ^ 1) * (VS_STG_F * 4);
#pragma unroll
            for (int it = 0; it < 4; it++) {
                int row = lrow + it * 16;
                cp_async16(smKraw + (uint32_t)(row * 64 + lc4) * 4,
                           Kn + (size_t)row * HDIM + lc4);
                cp_async16(vB + (uint32_t)(row * VS_STRIDE + lc4) * 4,
                           Vn + (size_t)row * HDIM + lc4);
            }
            CP_COMMIT();
        }

        const float* Vs = VsB + cur * VS_STG_F;

        // S = Q K^T  — per nt: 4 LDS.128 -> kb[16], then 8 chained mma
        float sc[8][4];
#pragma unroll
        for (int nt = 0; nt < 8; nt++)
#pragma unroll
            for (int q = 0; q < 4; q++) sc[nt][q] = 0.f;
#pragma unroll
        for (int nt = 0; nt < 8; nt++) {
            int key = nt * 8 + g;
            const float* kp = &KsP[key * 80 + 4 * tig];
            float kb[16];
            *(float4*)&kb[0]  = *(const float4*)(kp + 0);
            *(float4*)&kb[4]  = *(const float4*)(kp + 20);
            *(float4*)&kb[8]  = *(const float4*)(kp + 40);
            *(float4*)&kb[12] = *(const float4*)(kp + 60);
#pragma unroll
            for (int kc = 0; kc < 8; kc++)
                mma_tf32_16x8x8(sc[nt], qf[kc][0], qf[kc][1], qf[kc][2], qf[kc][3],
                                kb[2 * kc], kb[2 * kc + 1]);
        }

        // Online softmax (base-2).
        float rm0 = -1e30f, rm1 = -1e30f;
#pragma unroll
        for (int nt = 0; nt < 8; nt++) {
            rm0 = fmaxf(rm0, fmaxf(sc[nt][0], sc[nt][1]));
            rm1 = fmaxf(rm1, fmaxf(sc[nt][2], sc[nt][3]));
        }
        rm0 = fmaxf(rm0, __shfl_xor_sync(0xffffffffu, rm0, 1));
        rm0 = fmaxf(rm0, __shfl_xor_sync(0xffffffffu, rm0, 2));
        rm1 = fmaxf(rm1, __shfl_xor_sync(0xffffffffu, rm1, 1));
        rm1 = fmaxf(rm1, __shfl_xor_sync(0xffffffffu, rm1, 2));

        float nm0 = fmaxf(m0r, rm0);
        float nm1 = fmaxf(m1r, rm1);
        float alpha0 = ex2f(m0r - nm0);
        float alpha1 = ex2f(m1r - nm1);
        m0r = nm0; m1r = nm1;

        float rs0 = 0.f, rs1 = 0.f;
#pragma unroll
        for (int nt = 0; nt < 8; nt++) {
            sc[nt][0] = ex2f(sc[nt][0] - nm0);
            sc[nt][1] = ex2f(sc[nt][1] - nm0);
            sc[nt][2] = ex2f(sc[nt][2] - nm1);
            sc[nt][3] = ex2f(sc[nt][3] - nm1);
            rs0 += sc[nt][0] + sc[nt][1];
            rs1 += sc[nt][2] + sc[nt][3];
        }
        rs0 += __shfl_xor_sync(0xffffffffu, rs0, 1);
        rs0 += __shfl_xor_sync(0xffffffffu, rs0, 2);
        rs1 += __shfl_xor_sync(0xffffffffu, rs1, 1);
        rs1 += __shfl_xor_sync(0xffffffffu, rs1, 2);
        l0r = l0r * alpha0 + rs0;
        l1r = l1r * alpha1 + rs1;

#pragma unroll
        for (int nt = 0; nt < 8; nt++) {
            ov[nt][0] *= alpha0; ov[nt][1] *= alpha0;
            ov[nt][2] *= alpha1; ov[nt][3] *= alpha1;
        }

        // Stage P (RNA tf32) into per-warp slab
#pragma unroll
        for (int nt = 0; nt < 8; nt++) {
            float2 p0, p1;
            p0.x = f32_to_tf32f(sc[nt][0]); p0.y = f32_to_tf32f(sc[nt][1]);
            p1.x = f32_to_tf32f(sc[nt][2]); p1.y = f32_to_tf32f(sc[nt][3]);
            *(float2*)&Psw[g       * PS_STRIDE + nt * 8 + 2 * tig] = p0;
            *(float2*)&Psw[(g + 8) * PS_STRIDE + nt * 8 + 2 * tig] = p1;
        }
        __syncwarp();

        // O += P V  (unchanged)
#pragma unroll
        for (int kc = 0; kc < 8; kc++) {
            int k0 = kc * 8 + tig;
            float a0 = Psw[g       * PS_STRIDE + k0];
            float a1 = Psw[(g + 8) * PS_STRIDE + k0];
            float a2 = Psw[g       * PS_STRIDE + k0 + 4];
            float a3 = Psw[(g + 8) * PS_STRIDE + k0 + 4];
#pragma unroll
            for (int nt = 0; nt < 8; nt++) {
                float b0 = Vs[k0       * VS_STRIDE + nt * 8 + g];
                float b1 = Vs[(k0 + 4) * VS_STRIDE + nt * 8 + g];
                mma_tf32_16x8x8(ov[nt], a0, a1, a2, a3, b0, b1);
            }
        }
        // next iteration's first barrier provides the Vs/KsP reuse guard
    }

    // Epilogue: normalize, RNA-round (proj cp.async identity), store.
    float inv0 = 1.0f / l0r;
    float inv1 = 1.0f / l1r;
    int s0 = qrow + g;
    int s1 = qrow + g + 8;
#pragma unroll
    for (int nt = 0; nt < 8; nt++) {
        int d = nt * 8 + 2 * tig;
        float2 v0, v1;
        v0.x = f32_to_tf32f(ov[nt][0] * inv0); v0.y = f32_to_tf32f(ov[nt][1] * inv0);
        v1.x = f32_to_tf32f(ov[nt][2] * inv1); v1.y = f32_to_tf32f(ov[nt][3] * inv1);
        *(float2*)&g_attn[((size_t)(b * SEQ + s0)) * DMODEL + h * HDIM + d] = v0;
        *(float2*)&g_attn[((size_t)(b * SEQ + s1)) * DMODEL + h * HDIM + d] = v1;
    }
}

// ---------------------------------------------------------------------------
// Launch
// ---------------------------------------------------------------------------
extern "C" void kernel_launch(void* const* d_in, const int* in_sizes, int n_in,
                              void* d_out, int out_size)
{
    const float* x      = (const float*)d_in[0];
    const float* w_qkv  = (const float*)d_in[1];
    const float* b_qkv  = (const float*)d_in[2];
    const float* w_proj = (const float*)d_in[3];
    const float* b_proj = (const float*)d_in[4];
    float* out = (float*)d_out;

    cudaFuncSetAttribute(gemm_tc_kernel, cudaFuncAttributeMaxDynamicSharedMemorySize, GEMM_SMEM);
    cudaFuncSetAttribute(flash_tc_kernel, cudaFuncAttributeMaxDynamicSharedMemorySize, FLASH_SMEM);

    prep_round_kernel<<<(PREP_N4 + 255) / 256, 256>>>(x, w_qkv, w_proj);
    gemm_tc_kernel<<<dim3(QKV_N / 128, MTOT / 128), 256, GEMM_SMEM>>>(b_qkv, nullptr, 0);
    flash_tc_kernel<<<dim3(SEQ / 128, NHEAD, BATCH), 256, FLASH_SMEM>>>();
    gemm_tc_kernel<<<dim3(DMODEL / 128, MTOT / 128), 256, GEMM_SMEM>>>(b_proj, out, 1);
}

// round 15
// speedup vs baseline: 1.8633x; 1.8623x over previous
#include <cuda_runtime.h>
#include <cuda_fp16.h>
#include <math.h>
#include <stdint.h>

// Problem constants
#define BATCH 2
#define SEQ   2048
#define DMODEL 1024
#define NHEAD 16
#define HDIM  64
#define MTOT  (BATCH*SEQ)            // 4096
#define QKV_N (3*DMODEL)             // 3072
#define GK    1024

// fp16 scratch (allocation-free: __device__ globals)
__device__ __half g_hx[4194304u];        // rn(x)
__device__ __half g_hwqkv[3145728u];     // rn(w_qkv)
__device__ __half g_hwproj[1048576u];    // rn(w_proj)
__device__ __half g_hq[4194304u];        // [B*H][S][hd], pre-scaled by 0.125*log2e
__device__ __half g_hk[4194304u];        // [B*H][S][hd]
__device__ __half g_hv[4194304u];        // [B*H][kk=S/2][hd][2]  (key-pair packed)
__device__ __half g_hattn[4194304u];     // [B*S][H*hd]

__device__ __forceinline__ float ex2f(float x) {
    float r;
    asm("ex2.approx.ftz.f32 %0, %1;" : "=f"(r) : "f"(x));
    return r;
}

__device__ __forceinline__ uint32_t smem_u32(const void* p) {
    uint32_t a;
    asm("{ .reg .u64 t; cvta.to.shared.u64 t, %1; cvt.u32.u64 %0, t; }" : "=r"(a) : "l"(p));
    return a;
}

__device__ __forceinline__ void cp_async16(uint32_t dst_smem, const void* src) {
    asm volatile("cp.async.cg.shared.global [%0], [%1], 16;" :: "r"(dst_smem), "l"(src));
}
#define CP_COMMIT() asm volatile("cp.async.commit_group;" ::: "memory")
#define CP_WAIT(n)  asm volatile("cp.async.wait_group %0;" :: "n"(n) : "memory")

// fp16 MMA: D[16x8] += A[16x16] B[16x8], fp32 accumulate.
__device__ __forceinline__ void mma_f16(float* c,
                                        uint32_t a0, uint32_t a1, uint32_t a2, uint32_t a3,
                                        uint32_t b0, uint32_t b1) {
    asm volatile(
        "mma.sync.aligned.m16n8k16.row.col.f32.f16.f16.f32 "
        "{%0,%1,%2,%3}, {%4,%5,%6,%7}, {%8,%9}, {%0,%1,%2,%3};"
        : "+f"(c[0]), "+f"(c[1]), "+f"(c[2]), "+f"(c[3])
        : "r"(a0), "r"(a1), "r"(a2), "r"(a3), "r"(b0), "r"(b1));
}

// ---------------------------------------------------------------------------
// Prep: convert x, w_qkv, w_proj fp32 -> fp16 (RNE).
// ---------------------------------------------------------------------------
#define PREP_N4 2097152
__global__ __launch_bounds__(256) void prep_half_kernel(
    const float* __restrict__ x,
    const float* __restrict__ w_qkv,
    const float* __restrict__ w_proj)
{
    int i = blockIdx.x * 256 + threadIdx.x;
    if (i >= PREP_N4) return;
    const float4* src;
    __half* dst;
    if (i < 1048576) {
        src = (const float4*)x + i;
        dst = g_hx + (size_t)i * 4;
    } else if (i < 1048576 + 786432) {
        src = (const float4*)w_qkv + (i - 1048576);
        dst = g_hwqkv + (size_t)(i - 1048576) * 4;
    } else {
        src = (const float4*)w_proj + (i - 1048576 - 786432);
        dst = g_hwproj + (size_t)(i - 1048576 - 786432) * 4;
    }
    float4 v = *src;
    *(__half2*)(dst + 0) = __floats2half2_rn(v.x, v.y);
    *(__half2*)(dst + 2) = __floats2half2_rn(v.z, v.w);
}

// ---------------------------------------------------------------------------
// fp16 mma.sync GEMM: C[M,N] = A[M,K] @ W[N,K]^T + bias, K=1024.
// CTA 128x128, 8 warps (2x4), warp tile 64x32. K-tile 64 halves, 3-stage
// cp.async ring, depth-2 prefetch, one barrier/iter (R12-proven ordering).
// Smem rows: stride 72 halves (36 words; 4g+tig bank transversal).
// mode 0: A=g_hx, W=g_hwqkv -> scatter q (pre-scaled), k, v (pair-packed).
// mode 1: A=g_hattn, W=g_hwproj -> fp32 out.
// ---------------------------------------------------------------------------
#define GKT 64
#define A_STRIDE_H 72
#define G_STG_H   (128 * A_STRIDE_H)
#define G_STG_B   (G_STG_H * 2)          // 18432
#define GEMM_SMEM (3 * 2 * G_STG_B)      // 110592

#define QSCALE (0.125f * 1.4426950408889634f)

__global__ __launch_bounds__(256, 2) void gemm_h_kernel(
    const float* __restrict__ bias,
    float* __restrict__ out,
    int mode)
{
    extern __shared__ __half gsm_h[];
    __half* As = gsm_h;                  // [3][G_STG_H]
    __half* Bs = gsm_h + 3 * G_STG_H;    // [3][G_STG_H]

    const __half* A = (mode == 0) ? g_hx    : g_hattn;
    const __half* W = (mode == 0) ? g_hwqkv : g_hwproj;

    int tid  = threadIdx.x;
    int wid  = tid >> 5;
    int lane = tid & 31;
    int wm   = wid >> 2;
    int wn   = wid & 3;
    int g    = lane >> 2;
    int tig  = lane & 3;

    int m0 = blockIdx.y * 128;
    int n0 = blockIdx.x * 128;

    const __half* Ab = A + (size_t)m0 * GK;
    const __half* Wb = W + (size_t)n0 * GK;

    uint32_t smA = smem_u32(As);
    uint32_t smB = smem_u32(Bs);

    float c[4][4][4];
#pragma unroll
    for (int i = 0; i < 4; i++)
#pragma unroll
        for (int j = 0; j < 4; j++)
#pragma unroll
            for (int q = 0; q < 4; q++) c[i][j][q] = 0.f;

    const int NT = GK / GKT;   // 16

    auto issue_tile = [&](int t, int s) {
        int ko = t * GKT;                         // half offset
        uint32_t aB = smA + s * G_STG_B;
        uint32_t bB = smB + s * G_STG_B;
#pragma unroll
        for (int p = 0; p < 4; p++) {
            int id   = tid + p * 256;             // 0..1023
            int row  = id >> 3;                   // 0..127
            int c16  = id & 7;                    // 16B chunk (8 halves)
            uint32_t doff = (uint32_t)(row * A_STRIDE_H + c16 * 8) * 2;
            cp_async16(aB + doff, Ab + (size_t)row * GK + ko + c16 * 8);
            cp_async16(bB + doff, Wb + (size_t)row * GK + ko + c16 * 8);
        }
        CP_COMMIT();
    };

    issue_tile(0, 0);
    issue_tile(1, 1);

    int stg = 0;
    for (int kt = 0; kt < NT; kt++) {
        if (kt + 1 < NT) { CP_WAIT(1); } else { CP_WAIT(0); }
        __syncthreads();

        if (kt + 2 < NT) {
            int ws = stg + 2; if (ws >= 3) ws -= 3;
            issue_tile(kt + 2, ws);
        }

        const __half* as = As + stg * G_STG_H;
        const __half* bs = Bs + stg * G_STG_H;
#pragma unroll
        for (int kc = 0; kc < 4; kc++) {          // 4 x k16 steps
            int kh = kc * 16 + 2 * tig;
            uint32_t af[4][4], bf[4][2];
#pragma unroll
            for (int mt = 0; mt < 4; mt++) {
                int r = wm * 64 + mt * 16 + g;
                af[mt][0] = *(const uint32_t*)&as[(r + 0) * A_STRIDE_H + kh];
                af[mt][1] = *(const uint32_t*)&as[(r + 8) * A_STRIDE_H + kh];
                af[mt][2] = *(const uint32_t*)&as[(r + 0) * A_STRIDE_H + kh + 8];
                af[mt][3] = *(const uint32_t*)&as[(r + 8) * A_STRIDE_H + kh + 8];
            }
#pragma unroll
            for (int nt = 0; nt < 4; nt++) {
                int r = wn * 32 + nt * 8 + g;
                bf[nt][0] = *(const uint32_t*)&bs[r * A_STRIDE_H + kh];
                bf[nt][1] = *(const uint32_t*)&bs[r * A_STRIDE_H + kh + 8];
            }
#pragma unroll
            for (int mt = 0; mt < 4; mt++)
#pragma unroll
                for (int nt = 0; nt < 4; nt++)
                    mma_f16(c[mt][nt],
                            af[mt][0], af[mt][1], af[mt][2], af[mt][3],
                            bf[nt][0], bf[nt][1]);
        }
        stg = stg + 1; if (stg >= 3) stg = 0;
    }

    // Epilogue
#pragma unroll
    for (int mt = 0; mt < 4; mt++) {
#pragma unroll
        for (int half_ = 0; half_ < 2; half_++) {
            int m = m0 + wm * 64 + mt * 16 + g + half_ * 8;
            int b = m >> 11;
            int s = m & 2047;
#pragma unroll
            for (int nt = 0; nt < 4; nt++) {
                int n = n0 + wn * 32 + nt * 8 + 2 * tig;
                float vx = c[mt][nt][half_ * 2 + 0] + bias[n + 0];
                float vy = c[mt][nt][half_ * 2 + 1] + bias[n + 1];
                if (mode == 0) {
                    int which = n >> 10;
                    int rr = n & 1023;
                    int h = rr >> 6;
                    int d = rr & 63;
                    size_t bh = (size_t)((b << 4) + h);
                    if (which == 0) {
                        // Q: fold flash scale (0.125 * log2(e))
                        *(__half2*)&g_hq[(bh * SEQ + s) * HDIM + d] =
                            __floats2half2_rn(vx * QSCALE, vy * QSCALE);
                    } else if (which == 1) {
                        *(__half2*)&g_hk[(bh * SEQ + s) * HDIM + d] =
                            __floats2half2_rn(vx, vy);
                    } else {
                        // V: key-pair packed  v2[kk][d][par], kk=s/2, par=s&1
                        size_t base = bh * 131072u + (size_t)(s >> 1) * 128 + (s & 1);
                        g_hv[base + (size_t)d * 2]       = __float2half_rn(vx);
                        g_hv[base + (size_t)(d + 1) * 2] = __float2half_rn(vy);
                    }
                } else {
                    float2 v; v.x = vx; v.y = vy;
                    *(float2*)&out[(size_t)m * DMODEL + n] = v;
                }
            }
        }
    }
}

// ---------------------------------------------------------------------------
// Flash attention, fp16 mma (m16n8k16).
// CTA: 128 q-rows, 8 warps x 16 rows. 2-stage cp.async K/V ring, single
// barrier per tile (R13 ordering). K fragments contiguous along d (no
// repack); V arrives key-pair packed from GMEM so PV B-frags are 1 LDS.32.
// Smem: Ks[2][64][72h] | Vs2[2][32][72w] | Ps[128][72h] = 55296 B.
// ---------------------------------------------------------------------------
#define KS_H   72                       // K row stride, halves
#define VS_W   72                       // V2 row stride, words (half2)
#define PS_H   72                       // P row stride, halves
#define KS_STG_H (64 * KS_H)            // 4608 halves
#define VS_STG_W (32 * VS_W)            // 2304 words
#define FLASH_SMEM ((2*KS_STG_H + 2*2*VS_STG_W + 128*PS_H) * 2)

__global__ __launch_bounds__(256, 2) void flash_h_kernel()
{
    extern __shared__ __half smf_h[];
    __half*   KsB = smf_h;                                   // [2][KS_STG_H]
    uint32_t* VsB = (uint32_t*)(smf_h + 2 * KS_STG_H);       // [2][VS_STG_W]
    __half*   Ps  = smf_h + 2 * KS_STG_H + 2 * 2 * VS_STG_W; // [128][PS_H]

    int tid  = threadIdx.x;
    int w    = tid >> 5;
    int lane = tid & 31;
    int g    = lane >> 2;          // 0..7
    int tig  = lane & 3;           // 0..3

    int q0 = blockIdx.x * 128;
    int h  = blockIdx.y;
    int b  = blockIdx.z;

    size_t bh = (size_t)((b << 4) + h);
    const __half* Qh = g_hq + bh * SEQ * HDIM;
    const __half* Kh = g_hk + bh * SEQ * HDIM;
    const __half* Vh = g_hv + bh * 131072u;    // packed: [kk][64][2]

    uint32_t smK = smem_u32(KsB);
    uint32_t smV = smem_u32(VsB);

    // Q fragments, register-resident (pre-scaled at qkv epilogue)
    int qrow = q0 + w * 16;
    uint32_t qf[4][4];
#pragma unroll
    for (int kc = 0; kc < 4; kc++) {
        int d0 = kc * 16 + 2 * tig;
        qf[kc][0] = *(const uint32_t*)&Qh[(size_t)(qrow + g)     * HDIM + d0];
        qf[kc][1] = *(const uint32_t*)&Qh[(size_t)(qrow + g + 8) * HDIM + d0];
        qf[kc][2] = *(const uint32_t*)&Qh[(size_t)(qrow + g)     * HDIM + d0 + 8];
        qf[kc][3] = *(const uint32_t*)&Qh[(size_t)(qrow + g + 8) * HDIM + d0 + 8];
    }

    float m0r = -1e30f, m1r = -1e30f, l0r = 0.f, l1r = 0.f;
    float ov[8][4];
#pragma unroll
    for (int nt = 0; nt < 8; nt++)
#pragma unroll
        for (int q = 0; q < 4; q++) ov[nt][q] = 0.f;

    __half* Psw = Ps + w * 16 * PS_H;

    const int NT = SEQ / 64;   // 32

    auto issue_kv = [&](int t, int s) {
        const __half* Kt = Kh + (size_t)t * 64 * HDIM;
        const __half* Vt = Vh + (size_t)t * 4096;        // 32 kk-rows * 128 halves
        uint32_t kB = smK + s * (KS_STG_H * 2);
        uint32_t vB = smV + s * (VS_STG_W * 4);
#pragma unroll
        for (int p = 0; p < 2; p++) {
            int id  = tid + p * 256;                     // 0..511
            int kr  = id >> 3;                           // K: 0..63
            int kc16 = id & 7;
            cp_async16(kB + (uint32_t)(kr * KS_H + kc16 * 8) * 2,
                       Kt + (size_t)kr * HDIM + kc16 * 8);
            int vr  = id >> 4;                           // V: 0..31
            int vc16 = id & 15;
            cp_async16(vB + (uint32_t)(vr * VS_W * 4 + vc16 * 16),
                       Vt + (size_t)vr * 128 + vc16 * 8);
        }
        CP_COMMIT();
    };

    issue_kv(0, 0);

    for (int kt = 0; kt < NT; kt++) {
        int cur = kt & 1;

        CP_WAIT(0);
        __syncthreads();            // prev compute done; stage cur^1 free

        if (kt + 1 < NT) issue_kv(kt + 1, cur ^ 1);

        const __half*   Ks = KsB + cur * KS_STG_H;
        const uint32_t* Vs = VsB + cur * VS_STG_W;

        // S = Q K^T : per nt 8 LDS.32 + 4 chained mma
        float sc[8][4];
#pragma unroll
        for (int nt = 0; nt < 8; nt++)
#pragma unroll
            for (int q = 0; q < 4; q++) sc[nt][q] = 0.f;
#pragma unroll
        for (int nt = 0; nt < 8; nt++) {
            int key = nt * 8 + g;
            const __half* kp = &Ks[key * KS_H + 2 * tig];
#pragma unroll
            for (int kc = 0; kc < 4; kc++) {
                uint32_t b0 = *(const uint32_t*)(kp + kc * 16);
                uint32_t b1 = *(const uint32_t*)(kp + kc * 16 + 8);
                mma_f16(sc[nt], qf[kc][0], qf[kc][1], qf[kc][2], qf[kc][3], b0, b1);
            }
        }

        // Online softmax (base-2; scale folded into Q).
        float rm0 = -1e30f, rm1 = -1e30f;
#pragma unroll
        for (int nt = 0; nt < 8; nt++) {
            rm0 = fmaxf(rm0, fmaxf(sc[nt][0], sc[nt][1]));
            rm1 = fmaxf(rm1, fmaxf(sc[nt][2], sc[nt][3]));
        }
        rm0 = fmaxf(rm0, __shfl_xor_sync(0xffffffffu, rm0, 1));
        rm0 = fmaxf(rm0, __shfl_xor_sync(0xffffffffu, rm0, 2));
        rm1 = fmaxf(rm1, __shfl_xor_sync(0xffffffffu, rm1, 1));
        rm1 = fmaxf(rm1, __shfl_xor_sync(0xffffffffu, rm1, 2));

        float nm0 = fmaxf(m0r, rm0);
        float nm1 = fmaxf(m1r, rm1);
        float alpha0 = ex2f(m0r - nm0);
        float alpha1 = ex2f(m1r - nm1);
        m0r = nm0; m1r = nm1;

        float rs0 = 0.f, rs1 = 0.f;
#pragma unroll
        for (int nt = 0; nt < 8; nt++) {
            sc[nt][0] = ex2f(sc[nt][0] - nm0);
            sc[nt][1] = ex2f(sc[nt][1] - nm0);
            sc[nt][2] = ex2f(sc[nt][2] - nm1);
            sc[nt][3] = ex2f(sc[nt][3] - nm1);
            rs0 += sc[nt][0] + sc[nt][1];
            rs1 += sc[nt][2] + sc[nt][3];
        }
        rs0 += __shfl_xor_sync(0xffffffffu, rs0, 1);
        rs0 += __shfl_xor_sync(0xffffffffu, rs0, 2);
        rs1 += __shfl_xor_sync(0xffffffffu, rs1, 1);
        rs1 += __shfl_xor_sync(0xffffffffu, rs1, 2);
        l0r = l0r * alpha0 + rs0;
        l1r = l1r * alpha1 + rs1;

#pragma unroll
        for (int nt = 0; nt < 8; nt++) {
            ov[nt][0] *= alpha0; ov[nt][1] *= alpha0;
            ov[nt][2] *= alpha1; ov[nt][3] *= alpha1;
        }

        // Stage P as half2 into per-warp slab
#pragma unroll
        for (int nt = 0; nt < 8; nt++) {
            *(__half2*)&Psw[g       * PS_H + nt * 8 + 2 * tig] =
                __floats2half2_rn(sc[nt][0], sc[nt][1]);
            *(__half2*)&Psw[(g + 8) * PS_H + nt * 8 + 2 * tig] =
                __floats2half2_rn(sc[nt][2], sc[nt][3]);
        }
        __syncwarp();

        // O += P V : per kc 4 LDS.32 (P) ; per nt 2 LDS.32 (V pairs)
#pragma unroll
        for (int kc = 0; kc < 4; kc++) {
            int kh = kc * 16 + 2 * tig;
            uint32_t pa0 = *(const uint32_t*)&Psw[g       * PS_H + kh];
            uint32_t pa1 = *(const uint32_t*)&Psw[(g + 8) * PS_H + kh];
            uint32_t pa2 = *(const uint32_t*)&Psw[g       * PS_H + kh + 8];
            uint32_t pa3 = *(const uint32_t*)&Psw[(g + 8) * PS_H + kh + 8];
            int kk0 = kc * 8 + tig;          // b0 rows
#pragma unroll
            for (int nt = 0; nt < 8; nt++) {
                uint32_t b0 = Vs[kk0       * VS_W + nt * 8 + g];
                uint32_t b1 = Vs[(kk0 + 4) * VS_W + nt * 8 + g];
                mma_f16(ov[nt], pa0, pa1, pa2, pa3, b0, b1);
            }
        }
        // next iteration's barrier guards stage reuse
    }

    // Epilogue: normalize, store fp16 to g_hattn
    float inv0 = 1.0f / l0r;
    float inv1 = 1.0f / l1r;
    int s0 = qrow + g;
    int s1 = qrow + g + 8;
#pragma unroll
    for (int nt = 0; nt < 8; nt++) {
        int d = nt * 8 + 2 * tig;
        *(__half2*)&g_hattn[((size_t)(b * SEQ + s0)) * DMODEL + h * HDIM + d] =
            __floats2half2_rn(ov[nt][0] * inv0, ov[nt][1] * inv0);
        *(__half2*)&g_hattn[((size_t)(b * SEQ + s1)) * DMODEL + h * HDIM + d] =
            __floats2half2_rn(ov[nt][2] * inv1, ov[nt][3] * inv1);
    }
}

// ---------------------------------------------------------------------------
// Launch
// ---------------------------------------------------------------------------
extern "C" void kernel_launch(void* const* d_in, const int* in_sizes, int n_in,
                              void* d_out, int out_size)
{
    const float* x      = (const float*)d_in[0];
    const float* w_qkv  = (const float*)d_in[1];
    const float* b_qkv  = (const float*)d_in[2];
    const float* w_proj = (const float*)d_in[3];
    const float* b_proj = (const float*)d_in[4];
    float* out = (float*)d_out;

    cudaFuncSetAttribute(gemm_h_kernel, cudaFuncAttributeMaxDynamicSharedMemorySize, GEMM_SMEM);
    cudaFuncSetAttribute(flash_h_kernel, cudaFuncAttributeMaxDynamicSharedMemorySize, FLASH_SMEM);

    prep_half_kernel<<<(PREP_N4 + 255) / 256, 256>>>(x, w_qkv, w_proj);
    gemm_h_kernel<<<dim3(QKV_N / 128, MTOT / 128), 256, GEMM_SMEM>>>(b_qkv, nullptr, 0);
    flash_h_kernel<<<dim3(SEQ / 128, NHEAD, BATCH), 256, FLASH_SMEM>>>();
    gemm_h_kernel<<<dim3(DMODEL / 128, MTOT / 128), 256, GEMM_SMEM>>>(b_proj, out, 1);
}

// round 16
// speedup vs baseline: 1.9108x; 1.0255x over previous
#include <cuda_runtime.h>
#include <cuda_fp16.h>
#include <math.h>
#include <stdint.h>

// Problem constants
#define BATCH 2
#define SEQ   2048
#define DMODEL 1024
#define NHEAD 16
#define HDIM  64
#define MTOT  (BATCH*SEQ)            // 4096
#define QKV_N (3*DMODEL)             // 3072
#define GK    1024

// fp16 scratch (allocation-free: __device__ globals)
__device__ __half g_hx[4194304u];        // rn(x)
__device__ __half g_hwqkv[3145728u];     // rn(w_qkv)
__device__ __half g_hwproj[1048576u];    // rn(w_proj)
__device__ __half g_hq[4194304u];        // [B*H][S][hd], pre-scaled by 0.125*log2e
__device__ __half g_hk[4194304u];        // [B*H][S][hd]
__device__ __half g_hv[4194304u];        // [B*H][kk=S/2][hd][2]  (key-pair packed)
__device__ __half g_hattn[4194304u];     // [B*S][H*hd]

__device__ __forceinline__ float ex2f(float x) {
    float r;
    asm("ex2.approx.ftz.f32 %0, %1;" : "=f"(r) : "f"(x));
    return r;
}

__device__ __forceinline__ uint32_t smem_u32(const void* p) {
    uint32_t a;
    asm("{ .reg .u64 t; cvta.to.shared.u64 t, %1; cvt.u32.u64 %0, t; }" : "=r"(a) : "l"(p));
    return a;
}

__device__ __forceinline__ void cp_async16(uint32_t dst_smem, const void* src) {
    asm volatile("cp.async.cg.shared.global [%0], [%1], 16;" :: "r"(dst_smem), "l"(src));
}
#define CP_COMMIT() asm volatile("cp.async.commit_group;" ::: "memory")
#define CP_WAIT(n)  asm volatile("cp.async.wait_group %0;" :: "n"(n) : "memory")

// fp16 MMA: D[16x8] += A[16x16] B[16x8], fp32 accumulate.
__device__ __forceinline__ void mma_f16(float* c,
                                        uint32_t a0, uint32_t a1, uint32_t a2, uint32_t a3,
                                        uint32_t b0, uint32_t b1) {
    asm volatile(
        "mma.sync.aligned.m16n8k16.row.col.f32.f16.f16.f32 "
        "{%0,%1,%2,%3}, {%4,%5,%6,%7}, {%8,%9}, {%0,%1,%2,%3};"
        : "+f"(c[0]), "+f"(c[1]), "+f"(c[2]), "+f"(c[3])
        : "r"(a0), "r"(a1), "r"(a2), "r"(a3), "r"(b0), "r"(b1));
}

__device__ __forceinline__ void ldsm_x4(uint32_t& r0, uint32_t& r1, uint32_t& r2, uint32_t& r3,
                                        uint32_t addr) {
    asm volatile("ldmatrix.sync.aligned.m8n8.x4.shared.b16 {%0,%1,%2,%3}, [%4];"
                 : "=r"(r0), "=r"(r1), "=r"(r2), "=r"(r3) : "r"(addr));
}
__device__ __forceinline__ void ldsm_x2(uint32_t& r0, uint32_t& r1, uint32_t addr) {
    asm volatile("ldmatrix.sync.aligned.m8n8.x2.shared.b16 {%0,%1}, [%2];"
                 : "=r"(r0), "=r"(r1) : "r"(addr));
}

// ---------------------------------------------------------------------------
// Prep: convert x, w_qkv, w_proj fp32 -> fp16 (RNE).  (unchanged)
// ---------------------------------------------------------------------------
#define PREP_N4 2097152
__global__ __launch_bounds__(256) void prep_half_kernel(
    const float* __restrict__ x,
    const float* __restrict__ w_qkv,
    const float* __restrict__ w_proj)
{
    int i = blockIdx.x * 256 + threadIdx.x;
    if (i >= PREP_N4) return;
    const float4* src;
    __half* dst;
    if (i < 1048576) {
        src = (const float4*)x + i;
        dst = g_hx + (size_t)i * 4;
    } else if (i < 1048576 + 786432) {
        src = (const float4*)w_qkv + (i - 1048576);
        dst = g_hwqkv + (size_t)(i - 1048576) * 4;
    } else {
        src = (const float4*)w_proj + (i - 1048576 - 786432);
        dst = g_hwproj + (size_t)(i - 1048576 - 786432) * 4;
    }
    float4 v = *src;
    *(__half2*)(dst + 0) = __floats2half2_rn(v.x, v.y);
    *(__half2*)(dst + 2) = __floats2half2_rn(v.z, v.w);
}

// ---------------------------------------------------------------------------
// fp16 mma.sync GEMM — R16: fragment loads via ldmatrix (LDSM).
// A per (mt,kc): 1 ldmatrix.x4 (was 4 LDS.32); B per (nt,kc): 1 ldmatrix.x2
// (was 2 LDS.32). 96 -> 32 LSU ops per warp per k-tile. Everything else
// (3-stage cp.async ring, depth-2, K-tile 64) identical to R15 passing.
// ---------------------------------------------------------------------------
#define GKT 64
#define A_STRIDE_H 72
#define G_STG_H   (128 * A_STRIDE_H)
#define G_STG_B   (G_STG_H * 2)          // 18432
#define GEMM_SMEM (3 * 2 * G_STG_B)      // 110592

#define QSCALE (0.125f * 1.4426950408889634f)

__global__ __launch_bounds__(256, 2) void gemm_h_kernel(
    const float* __restrict__ bias,
    float* __restrict__ out,
    int mode)
{
    extern __shared__ __half gsm_h[];
    __half* As = gsm_h;                  // [3][G_STG_H]
    __half* Bs = gsm_h + 3 * G_STG_H;    // [3][G_STG_H]

    const __half* A = (mode == 0) ? g_hx    : g_hattn;
    const __half* W = (mode == 0) ? g_hwqkv : g_hwproj;

    int tid  = threadIdx.x;
    int wid  = tid >> 5;
    int lane = tid & 31;
    int wm   = wid >> 2;
    int wn   = wid & 3;
    int g    = lane >> 2;
    int tig  = lane & 3;

    int m0 = blockIdx.y * 128;
    int n0 = blockIdx.x * 128;

    const __half* Ab = A + (size_t)m0 * GK;
    const __half* Wb = W + (size_t)n0 * GK;

    uint32_t smA = smem_u32(As);
    uint32_t smB = smem_u32(Bs);

    // ldmatrix lane-address offsets (bytes, within a stage):
    // A x4: lanes 0-7 -> rows m0-7 @k0 | 8-15 -> m8-15 @k0 | 16-23 -> m0-7 @k8 | 24-31 -> m8-15 @k8
    int a_row_l = (lane & 7) + ((lane >> 3) & 1) * 8;
    int a_col_l = (lane >> 4) * 8;             // halves
    // B x2: lanes 0-7 -> n-rows @k0 | 8-15 -> @k8 (lanes 16-31 addresses unused; keep valid)
    int b_row_l = lane & 7;
    int b_col_l = ((lane >> 3) & 1) * 8;
    uint32_t a_off[4], b_off[4];
#pragma unroll
    for (int mt = 0; mt < 4; mt++)
        a_off[mt] = (uint32_t)(((wm * 64 + mt * 16 + a_row_l) * A_STRIDE_H + a_col_l) * 2);
#pragma unroll
    for (int nt = 0; nt < 4; nt++)
        b_off[nt] = (uint32_t)(((wn * 32 + nt * 8 + b_row_l) * A_STRIDE_H + b_col_l) * 2);

    float c[4][4][4];
#pragma unroll
    for (int i = 0; i < 4; i++)
#pragma unroll
        for (int j = 0; j < 4; j++)
#pragma unroll
            for (int q = 0; q < 4; q++) c[i][j][q] = 0.f;

    const int NT = GK / GKT;   // 16

    auto issue_tile = [&](int t, int s) {
        int ko = t * GKT;                         // half offset
        uint32_t aB = smA + s * G_STG_B;
        uint32_t bB = smB + s * G_STG_B;
#pragma unroll
        for (int p = 0; p < 4; p++) {
            int id   = tid + p * 256;             // 0..1023
            int row  = id >> 3;                   // 0..127
            int c16  = id & 7;                    // 16B chunk (8 halves)
            uint32_t doff = (uint32_t)(row * A_STRIDE_H + c16 * 8) * 2;
            cp_async16(aB + doff, Ab + (size_t)row * GK + ko + c16 * 8);
            cp_async16(bB + doff, Wb + (size_t)row * GK + ko + c16 * 8);
        }
        CP_COMMIT();
    };

    issue_tile(0, 0);
    issue_tile(1, 1);

    int stg = 0;
    for (int kt = 0; kt < NT; kt++) {
        if (kt + 1 < NT) { CP_WAIT(1); } else { CP_WAIT(0); }
        __syncthreads();

        if (kt + 2 < NT) {
            int ws = stg + 2; if (ws >= 3) ws -= 3;
            issue_tile(kt + 2, ws);
        }

        uint32_t aStg = smA + stg * G_STG_B;
        uint32_t bStg = smB + stg * G_STG_B;
#pragma unroll
        for (int kc = 0; kc < 4; kc++) {          // 4 x k16 steps; +32B per step
            uint32_t kofs = (uint32_t)(kc * 16 * 2);
            uint32_t af[4][4], bf[4][2];
#pragma unroll
            for (int mt = 0; mt < 4; mt++)
                ldsm_x4(af[mt][0], af[mt][1], af[mt][2], af[mt][3],
                        aStg + a_off[mt] + kofs);
#pragma unroll
            for (int nt = 0; nt < 4; nt++)
                ldsm_x2(bf[nt][0], bf[nt][1], bStg + b_off[nt] + kofs);
#pragma unroll
            for (int mt = 0; mt < 4; mt++)
#pragma unroll
                for (int nt = 0; nt < 4; nt++)
                    mma_f16(c[mt][nt],
                            af[mt][0], af[mt][1], af[mt][2], af[mt][3],
                            bf[nt][0], bf[nt][1]);
        }
        stg = stg + 1; if (stg >= 3) stg = 0;
    }

    // Epilogue (unchanged from R15)
#pragma unroll
    for (int mt = 0; mt < 4; mt++) {
#pragma unroll
        for (int half_ = 0; half_ < 2; half_++) {
            int m = m0 + wm * 64 + mt * 16 + g + half_ * 8;
            int b = m >> 11;
            int s = m & 2047;
#pragma unroll
            for (int nt = 0; nt < 4; nt++) {
                int n = n0 + wn * 32 + nt * 8 + 2 * tig;
                float vx = c[mt][nt][half_ * 2 + 0] + bias[n + 0];
                float vy = c[mt][nt][half_ * 2 + 1] + bias[n + 1];
                if (mode == 0) {
                    int which = n >> 10;
                    int rr = n & 1023;
                    int h = rr >> 6;
                    int d = rr & 63;
                    size_t bh = (size_t)((b << 4) + h);
                    if (which == 0) {
                        *(__half2*)&g_hq[(bh * SEQ + s) * HDIM + d] =
                            __floats2half2_rn(vx * QSCALE, vy * QSCALE);
                    } else if (which == 1) {
                        *(__half2*)&g_hk[(bh * SEQ + s) * HDIM + d] =
                            __floats2half2_rn(vx, vy);
                    } else {
                        size_t base = bh * 131072u + (size_t)(s >> 1) * 128 + (s & 1);
                        g_hv[base + (size_t)d * 2]       = __float2half_rn(vx);
                        g_hv[base + (size_t)(d + 1) * 2] = __float2half_rn(vy);
                    }
                } else {
                    float2 v; v.x = vx; v.y = vy;
                    *(float2*)&out[(size_t)m * DMODEL + n] = v;
                }
            }
        }
    }
}

// ---------------------------------------------------------------------------
// Flash attention, fp16 mma (m16n8k16) — unchanged from R15 passing version.
// ---------------------------------------------------------------------------
#define KS_H   72
#define VS_W   72
#define PS_H   72
#define KS_STG_H (64 * KS_H)
#define VS_STG_W (32 * VS_W)
#define FLASH_SMEM ((2*KS_STG_H + 2*2*VS_STG_W + 128*PS_H) * 2)

__global__ __launch_bounds__(256, 2) void flash_h_kernel()
{
    extern __shared__ __half smf_h[];
    __half*   KsB = smf_h;                                   // [2][KS_STG_H]
    uint32_t* VsB = (uint32_t*)(smf_h + 2 * KS_STG_H);       // [2][VS_STG_W]
    __half*   Ps  = smf_h + 2 * KS_STG_H + 2 * 2 * VS_STG_W; // [128][PS_H]

    int tid  = threadIdx.x;
    int w    = tid >> 5;
    int lane = tid & 31;
    int g    = lane >> 2;
    int tig  = lane & 3;

    int q0 = blockIdx.x * 128;
    int h  = blockIdx.y;
    int b  = blockIdx.z;

    size_t bh = (size_t)((b << 4) + h);
    const __half* Qh = g_hq + bh * SEQ * HDIM;
    const __half* Kh = g_hk + bh * SEQ * HDIM;
    const __half* Vh = g_hv + bh * 131072u;

    uint32_t smK = smem_u32(KsB);
    uint32_t smV = smem_u32(VsB);

    int qrow = q0 + w * 16;
    uint32_t qf[4][4];
#pragma unroll
    for (int kc = 0; kc < 4; kc++) {
        int d0 = kc * 16 + 2 * tig;
        qf[kc][0] = *(const uint32_t*)&Qh[(size_t)(qrow + g)     * HDIM + d0];
        qf[kc][1] = *(const uint32_t*)&Qh[(size_t)(qrow + g + 8) * HDIM + d0];
        qf[kc][2] = *(const uint32_t*)&Qh[(size_t)(qrow + g)     * HDIM + d0 + 8];
        qf[kc][3] = *(const uint32_t*)&Qh[(size_t)(qrow + g + 8) * HDIM + d0 + 8];
    }

    float m0r = -1e30f, m1r = -1e30f, l0r = 0.f, l1r = 0.f;
    float ov[8][4];
#pragma unroll
    for (int nt = 0; nt < 8; nt++)
#pragma unroll
        for (int q = 0; q < 4; q++) ov[nt][q] = 0.f;

    __half* Psw = Ps + w * 16 * PS_H;

    const int NT = SEQ / 64;   // 32

    auto issue_kv = [&](int t, int s) {
        const __half* Kt = Kh + (size_t)t * 64 * HDIM;
        const __half* Vt = Vh + (size_t)t * 4096;
        uint32_t kB = smK + s * (KS_STG_H * 2);
        uint32_t vB = smV + s * (VS_STG_W * 4);
#pragma unroll
        for (int p = 0; p < 2; p++) {
            int id  = tid + p * 256;
            int kr  = id >> 3;
            int kc16 = id & 7;
            cp_async16(kB + (uint32_t)(kr * KS_H + kc16 * 8) * 2,
                       Kt + (size_t)kr * HDIM + kc16 * 8);
            int vr  = id >> 4;
            int vc16 = id & 15;
            cp_async16(vB + (uint32_t)(vr * VS_W * 4 + vc16 * 16),
                       Vt + (size_t)vr * 128 + vc16 * 8);
        }
        CP_COMMIT();
    };

    issue_kv(0, 0);

    for (int kt = 0; kt < NT; kt++) {
        int cur = kt & 1;

        CP_WAIT(0);
        __syncthreads();

        if (kt + 1 < NT) issue_kv(kt + 1, cur ^ 1);

        const __half*   Ks = KsB + cur * KS_STG_H;
        const uint32_t* Vs = VsB + cur * VS_STG_W;

        float sc[8][4];
#pragma unroll
        for (int nt = 0; nt < 8; nt++)
#pragma unroll
            for (int q = 0; q < 4; q++) sc[nt][q] = 0.f;
#pragma unroll
        for (int nt = 0; nt < 8; nt++) {
            int key = nt * 8 + g;
            const __half* kp = &Ks[key * KS_H + 2 * tig];
#pragma unroll
            for (int kc = 0; kc < 4; kc++) {
                uint32_t b0 = *(const uint32_t*)(kp + kc * 16);
                uint32_t b1 = *(const uint32_t*)(kp + kc * 16 + 8);
                mma_f16(sc[nt], qf[kc][0], qf[kc][1], qf[kc][2], qf[kc][3], b0, b1);
            }
        }

        float rm0 = -1e30f, rm1 = -1e30f;
#pragma unroll
        for (int nt = 0; nt < 8; nt++) {
            rm0 = fmaxf(rm0, fmaxf(sc[nt][0], sc[nt][1]));
            rm1 = fmaxf(rm1, fmaxf(sc[nt][2], sc[nt][3]));
        }
        rm0 = fmaxf(rm0, __shfl_xor_sync(0xffffffffu, rm0, 1));
        rm0 = fmaxf(rm0, __shfl_xor_sync(0xffffffffu, rm0, 2));
        rm1 = fmaxf(rm1, __shfl_xor_sync(0xffffffffu, rm1, 1));
        rm1 = fmaxf(rm1, __shfl_xor_sync(0xffffffffu, rm1, 2));

        float nm0 = fmaxf(m0r, rm0);
        float nm1 = fmaxf(m1r, rm1);
        float alpha0 = ex2f(m0r - nm0);
        float alpha1 = ex2f(m1r - nm1);
        m0r = nm0; m1r = nm1;

        float rs0 = 0.f, rs1 = 0.f;
#pragma unroll
        for (int nt = 0; nt < 8; nt++) {
            sc[nt][0] = ex2f(sc[nt][0] - nm0);
            sc[nt][1] = ex2f(sc[nt][1] - nm0);
            sc[nt][2] = ex2f(sc[nt][2] - nm1);
            sc[nt][3] = ex2f(sc[nt][3] - nm1);
            rs0 += sc[nt][0] + sc[nt][1];
            rs1 += sc[nt][2] + sc[nt][3];
        }
        rs0 += __shfl_xor_sync(0xffffffffu, rs0, 1);
        rs0 += __shfl_xor_sync(0xffffffffu, rs0, 2);
        rs1 += __shfl_xor_sync(0xffffffffu, rs1, 1);
        rs1 += __shfl_xor_sync(0xffffffffu, rs1, 2);
        l0r = l0r * alpha0 + rs0;
        l1r = l1r * alpha1 + rs1;

#pragma unroll
        for (int nt = 0; nt < 8; nt++) {
            ov[nt][0] *= alpha0; ov[nt][1] *= alpha0;
            ov[nt][2] *= alpha1; ov[nt][3] *= alpha1;
        }

#pragma unroll
        for (int nt = 0; nt < 8; nt++) {
            *(__half2*)&Psw[g       * PS_H + nt * 8 + 2 * tig] =
                __floats2half2_rn(sc[nt][0], sc[nt][1]);
            *(__half2*)&Psw[(g + 8) * PS_H + nt * 8 + 2 * tig] =
                __floats2half2_rn(sc[nt][2], sc[nt][3]);
        }
        __syncwarp();

#pragma unroll
        for (int kc = 0; kc < 4; kc++) {
            int kh = kc * 16 + 2 * tig;
            uint32_t pa0 = *(const uint32_t*)&Psw[g       * PS_H + kh];
            uint32_t pa1 = *(const uint32_t*)&Psw[(g + 8) * PS_H + kh];
            uint32_t pa2 = *(const uint32_t*)&Psw[g       * PS_H + kh + 8];
            uint32_t pa3 = *(const uint32_t*)&Psw[(g + 8) * PS_H + kh + 8];
            int kk0 = kc * 8 + tig;
#pragma unroll
            for (int nt = 0; nt < 8; nt++) {
                uint32_t b0 = Vs[kk0       * VS_W + nt * 8 + g];
                uint32_t b1 = Vs[(kk0 + 4) * VS_W + nt * 8 + g];
                mma_f16(ov[nt], pa0, pa1, pa2, pa3, b0, b1);
            }
        }
    }

    float inv0 = 1.0f / l0r;
    float inv1 = 1.0f / l1r;
    int s0 = qrow + g;
    int s1 = qrow + g + 8;
#pragma unroll
    for (int nt = 0; nt < 8; nt++) {
        int d = nt * 8 + 2 * tig;
        *(__half2*)&g_hattn[((size_t)(b * SEQ + s0)) * DMODEL + h * HDIM + d] =
            __floats2half2_rn(ov[nt][0] * inv0, ov[nt][1] * inv0);
        *(__half2*)&g_hattn[((size_t)(b * SEQ + s1)) * DMODEL + h * HDIM + d] =
            __floats2half2_rn(ov[nt][2] * inv1, ov[nt][3] * inv1);
    }
}

// ---------------------------------------------------------------------------
// Launch
// ---------------------------------------------------------------------------
extern "C" void kernel_launch(void* const* d_in, const int* in_sizes, int n_in,
                              void* d_out, int out_size)
{
    const float* x      = (const float*)d_in[0];
    const float* w_qkv  = (const float*)d_in[1];
    const float* b_qkv  = (const float*)d_in[2];
    const float* w_proj = (const float*)d_in[3];
    const float* b_proj = (const float*)d_in[4];
    float* out = (float*)d_out;

    cudaFuncSetAttribute(gemm_h_kernel, cudaFuncAttributeMaxDynamicSharedMemorySize, GEMM_SMEM);
    cudaFuncSetAttribute(flash_h_kernel, cudaFuncAttributeMaxDynamicSharedMemorySize, FLASH_SMEM);

    prep_half_kernel<<<(PREP_N4 + 255) / 256, 256>>>(x, w_qkv, w_proj);
    gemm_h_kernel<<<dim3(QKV_N / 128, MTOT / 128), 256, GEMM_SMEM>>>(b_qkv, nullptr, 0);
    flash_h_kernel<<<dim3(SEQ / 128, NHEAD, BATCH), 256, FLASH_SMEM>>>();
    gemm_h_kernel<<<dim3(DMODEL / 128, MTOT / 128), 256, GEMM_SMEM>>>(b_proj, out, 1);
}